// round 7
// baseline (speedup 1.0000x reference)
#include <cuda_runtime.h>
#include <cuda_bf16.h>
#include <cstdint>

// ---------------------------------------------------------------------------
// x:(2048,64,512) fp32, Wq/Wk/Wv/Wo:(512,512) fp32
// out = SDPA(x@WqT, x@WkT, x@WvT) @ WoT    H=16, dk=32, S=64
//
// mma.sync tf32 path (tcgen05 unavailable at compute_103).
// R7 changes vs R6:
//  * GEMM: fragment double-buffering across the 4 k-groups per stage
//    (hides LDS latency behind mma issue).
//  * GEMM epilogue can round-to-tf32 and pk8-permute its output columns:
//    QKV launch writes Q,K rounded+permuted and V rounded plain, so the
//    attention kernel stages Q/K/V with raw float4 copies (no cvt, no
//    scattered Q/K stores). Bit-identical math to R6.
// ---------------------------------------------------------------------------

#define D_MODEL   512
#define M_ROWS    131072
#define NUM_HEADS 16
#define SEQ       64
#define DK        32

#define MS        ((size_t)M_ROWS * D_MODEL)
#define WELEMS    ((size_t)D_MODEL * D_MODEL)

__device__ float g_xt[MS];           // x, tf32-rounded, pk8-permuted cols
__device__ float g_wt[4 * WELEMS];   // Wq,Wk,Wv,Wo, tf32-rounded, permuted
__device__ float g_qkv[3 * MS];      // q(perm), k(perm), v(plain); all rounded
__device__ float g_at[MS];           // attn out, tf32-rounded, permuted

// ======================== helpers ==========================================
__device__ __forceinline__ unsigned f2tf32(float f) {
    unsigned r;
    asm("cvt.rna.tf32.f32 %0, %1;" : "=r"(r) : "f"(f));
    return r;
}
__device__ __forceinline__ float rtf(float f) {
    return __uint_as_float(f2tf32(f));
}
__device__ __forceinline__ int pk8(int k) {
    return (k & ~7) + ((k & 3) << 1) + ((k & 7) >> 2);
}
__device__ __forceinline__ uint32_t smem_u32(const void* p) {
    uint32_t a;
    asm("{ .reg .u64 t; cvta.to.shared.u64 t, %1; cvt.u32.u64 %0, t; }"
        : "=r"(a) : "l"(p));
    return a;
}

#define MMA_TF32(d, a0, a1, a2, a3, b0, b1)                                    \
    asm volatile(                                                              \
        "mma.sync.aligned.m16n8k8.row.col.f32.tf32.tf32.f32 "                  \
        "{%0,%1,%2,%3}, {%4,%5,%6,%7}, {%8,%9}, {%0,%1,%2,%3};"                \
        : "+f"(d[0]), "+f"(d[1]), "+f"(d[2]), "+f"(d[3])                       \
        : "r"(a0), "r"(a1), "r"(a2), "r"(a3), "r"(b0), "r"(b1))

#define CPA16(sa, gp)                                                          \
    asm volatile("cp.async.cg.shared.global [%0], [%1], 16;"                   \
                 :: "r"(sa), "l"(gp) : "memory")
#define CPA_COMMIT() asm volatile("cp.async.commit_group;" ::: "memory")
#define CPA_WAIT1()  asm volatile("cp.async.wait_group 1;" ::: "memory")
#define CPA_WAIT0()  asm volatile("cp.async.wait_group 0;" ::: "memory")
#define LDS64(v, a)                                                            \
    asm volatile("ld.shared.v2.u32 {%0,%1}, [%2];"                             \
                 : "=r"((v).x), "=r"((v).y) : "r"(a))

// ======================== prep passes ======================================
__device__ __forceinline__ void prep_group(const float4* in, float4* out) {
    float4 u = in[0], v = in[1];
    out[0] = make_float4(rtf(u.x), rtf(v.x), rtf(u.y), rtf(v.y));
    out[1] = make_float4(rtf(u.z), rtf(v.z), rtf(u.w), rtf(v.w));
}

__global__ void __launch_bounds__(256)
prep_x_kernel(const float* __restrict__ in, float* __restrict__ out) {
    size_t g = (size_t)blockIdx.x * 256 + threadIdx.x;
    float4 o[2];
    prep_group((const float4*)in + 2 * g, o);
    ((float4*)out)[2 * g]     = o[0];
    ((float4*)out)[2 * g + 1] = o[1];
}

__global__ void __launch_bounds__(256)
prep_w_kernel(const float* __restrict__ w0, const float* __restrict__ w1,
              const float* __restrict__ w2, const float* __restrict__ w3,
              float* __restrict__ out) {
    size_t g = (size_t)blockIdx.x * 256 + threadIdx.x;
    int wsel = (int)(g >> 15);
    const float* src = wsel == 0 ? w0 : wsel == 1 ? w1 : wsel == 2 ? w2 : w3;
    size_t off = (g & 32767) * 8;
    float4 o[2];
    prep_group((const float4*)(src + off), o);
    ((float4*)out)[2 * g]     = o[0];
    ((float4*)out)[2 * g + 1] = o[1];
}

// ======================== GEMM (tf32 mma.sync, cp.async x3 stages) =========
// Block 128x128, BK=32, 128 threads = 4 warps (2M x 2N), warp 64x64.
// Fragment double-buffering across the 4 k-groups of each stage.
#define GSTAGE  32768
#define GSMEM   (3 * GSTAGE + 128)

__global__ void __launch_bounds__(128, 2)
gemm_tf32(const float* __restrict__ A, const float* __restrict__ Wt,
          float* __restrict__ C, size_t c_stride,
          uint32_t perm_mask, uint32_t round_mask) {
    extern __shared__ char dsmem[];
    const uint32_t sb = (smem_u32(dsmem) + 127u) & ~127u;

    const int tid  = threadIdx.x;
    const int lane = tid & 31;
    const int wid  = tid >> 5;
    const int wm   = wid & 1;
    const int wn   = wid >> 1;
    const int c    = lane & 3;
    const int r8   = lane >> 2;

    const int nb   = blockIdx.x;
    const int wsel = nb >> 2;
    const int n0   = (nb & 3) * 128;
    const int m0   = blockIdx.y * 128;

    const float* Aw = A + (size_t)m0 * 512;
    const float* Bw = Wt + (size_t)wsel * WELEMS + (size_t)n0 * 512;
    float* Cw = C + (size_t)wsel * c_stride;

    float acc[4][8][4];
#pragma unroll
    for (int mt = 0; mt < 4; mt++)
#pragma unroll
        for (int nt = 0; nt < 8; nt++)
#pragma unroll
            for (int i = 0; i < 4; i++) acc[mt][nt][i] = 0.0f;

    auto load_stage = [&](int s, int kt) {
        const uint32_t stage = sb + s * GSTAGE;
#pragma unroll
        for (int i = 0; i < 16; i++) {
            const int cid = tid + i * 128;
            const int isB = cid >> 10;
            const int r   = (cid >> 3) & 127;
            const int ch  = cid & 7;
            const uint32_t so =
                stage + isB * 16384 + r * 128 + (((ch ^ (r & 7)) << 4));
            const float* gp =
                (isB ? Bw : Aw) + (size_t)r * 512 + kt * 32 + ch * 4;
            CPA16(so, gp);
        }
        CPA_COMMIT();
    };

    unsigned a0[2][4], a1[2][4], a2[2][4], a3[2][4], b0[2][8], b1[2][8];

    auto compute = [&](int s) {
        const uint32_t sA = sb + s * GSTAGE + (wm * 64 + r8) * 128 + 8 * (c & 1);
        const uint32_t sB = sb + s * GSTAGE + 16384 + wn * 8192 + r8 * 128 +
                            8 * (c & 1);
        auto ldfrag = [&](int g, int bf) {
            const uint32_t csw = (uint32_t)(((2 * g + (c >> 1)) ^ r8) << 4);
            uint2 lo, hi;
#pragma unroll
            for (int mt = 0; mt < 4; mt++) {
                LDS64(lo, sA + mt * 2048 + csw);
                LDS64(hi, sA + mt * 2048 + 1024 + csw);
                a0[bf][mt] = lo.x; a2[bf][mt] = lo.y;
                a1[bf][mt] = hi.x; a3[bf][mt] = hi.y;
            }
#pragma unroll
            for (int nt = 0; nt < 8; nt++) {
                LDS64(lo, sB + nt * 1024 + csw);
                b0[bf][nt] = lo.x; b1[bf][nt] = lo.y;
            }
        };
        ldfrag(0, 0);
#pragma unroll
        for (int g = 0; g < 4; g++) {
            const int bf = g & 1;
            if (g < 3) ldfrag(g + 1, bf ^ 1);
#pragma unroll
            for (int mt = 0; mt < 4; mt++)
#pragma unroll
                for (int nt = 0; nt < 8; nt++)
                    MMA_TF32(acc[mt][nt], a0[bf][mt], a1[bf][mt], a2[bf][mt],
                             a3[bf][mt], b0[bf][nt], b1[bf][nt]);
        }
    };

    load_stage(0, 0);
    load_stage(1, 1);

    int scur = 0, snext = 1, sload = 2;
#pragma unroll 1
    for (int kt = 0; kt < 16; kt++) {
        if (kt < 15) { CPA_WAIT1(); } else { CPA_WAIT0(); }
        __syncthreads();
        if (kt + 2 < 16) load_stage(sload, kt + 2);
        compute(scur);
        const int t = scur; scur = snext; snext = sload; sload = t;
    }

    // Epilogue. perm: round + pk8-permute cols (attention Q/K input layout).
    // rnd: round only (V). neither: plain fp32 (final output).
    const bool perm = (perm_mask >> wsel) & 1u;
    const bool rnd  = (round_mask >> wsel) & 1u;
    const int j0 = 2 * c;
    const int p0 = ((j0 & 3) << 1) + (j0 >> 2);
    const int p1 = (((j0 + 1) & 3) << 1) + ((j0 + 1) >> 2);
#pragma unroll
    for (int mt = 0; mt < 4; mt++) {
        const int row = m0 + wm * 64 + mt * 16 + r8;
#pragma unroll
        for (int nt = 0; nt < 8; nt++) {
            const int colb = n0 + wn * 64 + nt * 8;
            float* r0 = &Cw[(size_t)row * 512 + colb];
            float* r1 = &Cw[(size_t)(row + 8) * 512 + colb];
            if (perm) {
                r0[p0] = rtf(acc[mt][nt][0]);
                r0[p1] = rtf(acc[mt][nt][1]);
                r1[p0] = rtf(acc[mt][nt][2]);
                r1[p1] = rtf(acc[mt][nt][3]);
            } else if (rnd) {
                *(float2*)(r0 + j0) =
                    make_float2(rtf(acc[mt][nt][0]), rtf(acc[mt][nt][1]));
                *(float2*)(r1 + j0) =
                    make_float2(rtf(acc[mt][nt][2]), rtf(acc[mt][nt][3]));
            } else {
                *(float2*)(r0 + j0) =
                    make_float2(acc[mt][nt][0], acc[mt][nt][1]);
                *(float2*)(r1 + j0) =
                    make_float2(acc[mt][nt][2], acc[mt][nt][3]);
            }
        }
    }
}

// ======================== attention (tf32 mma.sync) ========================
// Q,K arrive rounded + pk8-permuted; V arrives rounded plain.
__global__ void __launch_bounds__(128, 7)
attn64_tf32(const float* __restrict__ Q, const float* __restrict__ K,
            const float* __restrict__ V, float* __restrict__ At) {
    __shared__ union {
        struct { unsigned Q[64][36]; unsigned K[64][36]; } qk;
        unsigned P[4][16][68];
    } u;
    __shared__ unsigned Vt[32][68];

    const int tid  = threadIdx.x;
    const int lane = tid & 31;
    const int w    = tid >> 5;
    const int c    = lane & 3;
    const int r8   = lane >> 2;

    const int bh = blockIdx.x;
    const int b  = bh >> 4;
    const int h  = bh & 15;
    const size_t rbase = (size_t)b * SEQ * D_MODEL + h * DK;

    const int lrow = tid >> 1;
    const int lc0  = (tid & 1) * 16;
    const int prow = pk8(lrow);
#pragma unroll
    for (int q = 0; q < 4; q++) {
        float4 vq = *(const float4*)(Q + rbase + (size_t)lrow * D_MODEL + lc0 + q * 4);
        float4 vk = *(const float4*)(K + rbase + (size_t)lrow * D_MODEL + lc0 + q * 4);
        float4 vv = *(const float4*)(V + rbase + (size_t)lrow * D_MODEL + lc0 + q * 4);
        *(float4*)&u.qk.Q[lrow][lc0 + q * 4] = vq;   // already rounded+permuted
        *(float4*)&u.qk.K[lrow][lc0 + q * 4] = vk;
        const float av[4] = {vv.x, vv.y, vv.z, vv.w};
#pragma unroll
        for (int j = 0; j < 4; j++)
            Vt[lc0 + q * 4 + j][prow] = __float_as_uint(av[j]);
    }
    __syncthreads();

    float s[8][4];
#pragma unroll
    for (int nt = 0; nt < 8; nt++)
#pragma unroll
        for (int i = 0; i < 4; i++) s[nt][i] = 0.0f;

#pragma unroll
    for (int kk = 0; kk < 32; kk += 8) {
        const int kpos = kk + 2 * c;
        uint2 alo = *(const uint2*)&u.qk.Q[w * 16 + r8][kpos];
        uint2 ahi = *(const uint2*)&u.qk.Q[w * 16 + 8 + r8][kpos];
#pragma unroll
        for (int nt = 0; nt < 8; nt++) {
            uint2 bb = *(const uint2*)&u.qk.K[nt * 8 + r8][kpos];
            MMA_TF32(s[nt], alo.x, ahi.x, alo.y, ahi.y, bb.x, bb.y);
        }
    }

    const float scale = 0.17677669529663687f;  // 1/sqrt(32)
#pragma unroll
    for (int nt = 0; nt < 8; nt++)
#pragma unroll
        for (int i = 0; i < 4; i++) s[nt][i] *= scale;

    float m1 = -1e30f, m2 = -1e30f;
#pragma unroll
    for (int nt = 0; nt < 8; nt++) {
        m1 = fmaxf(m1, fmaxf(s[nt][0], s[nt][1]));
        m2 = fmaxf(m2, fmaxf(s[nt][2], s[nt][3]));
    }
    m1 = fmaxf(m1, __shfl_xor_sync(0xffffffffu, m1, 1));
    m1 = fmaxf(m1, __shfl_xor_sync(0xffffffffu, m1, 2));
    m2 = fmaxf(m2, __shfl_xor_sync(0xffffffffu, m2, 1));
    m2 = fmaxf(m2, __shfl_xor_sync(0xffffffffu, m2, 2));

    float sum1 = 0.0f, sum2 = 0.0f;
#pragma unroll
    for (int nt = 0; nt < 8; nt++) {
        s[nt][0] = __expf(s[nt][0] - m1);
        s[nt][1] = __expf(s[nt][1] - m1);
        s[nt][2] = __expf(s[nt][2] - m2);
        s[nt][3] = __expf(s[nt][3] - m2);
        sum1 += s[nt][0] + s[nt][1];
        sum2 += s[nt][2] + s[nt][3];
    }
    sum1 += __shfl_xor_sync(0xffffffffu, sum1, 1);
    sum1 += __shfl_xor_sync(0xffffffffu, sum1, 2);
    sum2 += __shfl_xor_sync(0xffffffffu, sum2, 1);
    sum2 += __shfl_xor_sync(0xffffffffu, sum2, 2);
    const float inv1 = 1.0f / sum1;
    const float inv2 = 1.0f / sum2;

    // All warps must be done reading Qs/Ks before Ps overlays them.
    __syncthreads();

    const int j0 = 2 * c;
    const int p0 = ((j0 & 3) << 1) + (j0 >> 2);
    const int p1 = (((j0 + 1) & 3) << 1) + ((j0 + 1) >> 2);
#pragma unroll
    for (int nt = 0; nt < 8; nt++) {
        u.P[w][r8][nt * 8 + p0]     = f2tf32(s[nt][0] * inv1);
        u.P[w][r8][nt * 8 + p1]     = f2tf32(s[nt][1] * inv1);
        u.P[w][r8 + 8][nt * 8 + p0] = f2tf32(s[nt][2] * inv2);
        u.P[w][r8 + 8][nt * 8 + p1] = f2tf32(s[nt][3] * inv2);
    }
    __syncwarp();

    float o[4][4];
#pragma unroll
    for (int nt = 0; nt < 4; nt++)
#pragma unroll
        for (int i = 0; i < 4; i++) o[nt][i] = 0.0f;

#pragma unroll
    for (int kk = 0; kk < 64; kk += 8) {
        const int kpos = kk + 2 * c;
        uint2 alo = *(const uint2*)&u.P[w][r8][kpos];
        uint2 ahi = *(const uint2*)&u.P[w][r8 + 8][kpos];
#pragma unroll
        for (int nt = 0; nt < 4; nt++) {
            uint2 bb = *(const uint2*)&Vt[nt * 8 + r8][kpos];
            MMA_TF32(o[nt], alo.x, ahi.x, alo.y, ahi.y, bb.x, bb.y);
        }
    }

    // Epilogue: tf32-rounded, pk8-permuted store (Wo-GEMM input layout).
    const int row = b * SEQ + w * 16 + r8;
#pragma unroll
    for (int nt = 0; nt < 4; nt++) {
        const int cb = h * DK + nt * 8;
        At[(size_t)row * D_MODEL + cb + p0]       = rtf(o[nt][0]);
        At[(size_t)row * D_MODEL + cb + p1]       = rtf(o[nt][1]);
        At[(size_t)(row + 8) * D_MODEL + cb + p0] = rtf(o[nt][2]);
        At[(size_t)(row + 8) * D_MODEL + cb + p1] = rtf(o[nt][3]);
    }
}

// ======================== launch ===========================================
extern "C" void kernel_launch(void* const* d_in, const int* in_sizes, int n_in,
                              void* d_out, int out_size) {
    (void)in_sizes; (void)n_in; (void)out_size;
    const float* x  = (const float*)d_in[0];
    const float* Wq = (const float*)d_in[1];
    const float* Wk = (const float*)d_in[2];
    const float* Wv = (const float*)d_in[3];
    const float* Wo = (const float*)d_in[4];
    float* out = (float*)d_out;

    void *pxt, *pwt, *pqkv, *pat;
    cudaGetSymbolAddress(&pxt, g_xt);
    cudaGetSymbolAddress(&pwt, g_wt);
    cudaGetSymbolAddress(&pqkv, g_qkv);
    cudaGetSymbolAddress(&pat, g_at);

    cudaFuncSetAttribute(gemm_tf32,
                         cudaFuncAttributeMaxDynamicSharedMemorySize, GSMEM);

    prep_w_kernel<<<512, 256>>>(Wq, Wk, Wv, Wo, (float*)pwt);
    prep_x_kernel<<<32768, 256>>>(x, (float*)pxt);

    // Fused Q,K,V projections: Q,K rounded+permuted; V rounded plain.
    gemm_tf32<<<dim3(12, M_ROWS / 128), 128, GSMEM>>>(
        (const float*)pxt, (const float*)pwt, (float*)pqkv, MS,
        /*perm_mask=*/0b011u, /*round_mask=*/0b111u);

    const float* q = (const float*)pqkv;
    const float* k = q + MS;
    const float* v = k + MS;
    attn64_tf32<<<M_ROWS / SEQ * NUM_HEADS, 128>>>(q, k, v, (float*)pat);

    // Output projection: plain fp32 output.
    gemm_tf32<<<dim3(4, M_ROWS / 128), 128, GSMEM>>>(
        (const float*)pat, (const float*)pwt + 3 * WELEMS, out, 0,
        0u, 0u);
}

// round 8
// speedup vs baseline: 1.8230x; 1.8230x over previous
#include <cuda_runtime.h>
#include <cuda_fp16.h>
#include <cstdint>

// ---------------------------------------------------------------------------
// x:(2048,64,512) fp32, Wq/Wk/Wv/Wo:(512,512) fp32
// out = SDPA(x@WqT, x@WkT, x@WvT) @ WoT    H=16, dk=32, S=64
//
// R8: full fp16 mma.sync m16n8k16 pipeline (fp32 accum). fp16 RN has the
// same 11-bit mantissa as tf32 -> same error class, half the mma count and
// half the SMEM traffic. Operands pre-rounded to fp16 and PAIR-permuted
// within groups of 16 halves (pair j -> slot ((j&3)<<1)+(j>>2)) so every
// mma fragment is a single LDS.64.
// ---------------------------------------------------------------------------

#define D_MODEL   512
#define M_ROWS    131072
#define NUM_HEADS 16
#define SEQ       64
#define DK        32

#define MS        ((size_t)M_ROWS * D_MODEL)
#define WELEMS    ((size_t)D_MODEL * D_MODEL)

__device__ __half g_xh[MS];            // x, fp16, pair-permuted along k
__device__ __half g_wh[4 * WELEMS];    // Wq,Wk,Wv,Wo fp16, pair-permuted
__device__ __half g_qkvh[3 * MS];      // q(perm), k(perm), v(plain)
__device__ __half g_ath[MS];           // attn out fp16, pair-permuted

// ======================== helpers ==========================================
__device__ __forceinline__ uint32_t smem_u32(const void* p) {
    uint32_t a;
    asm("{ .reg .u64 t; cvta.to.shared.u64 t, %1; cvt.u32.u64 %0, t; }"
        : "=r"(a) : "l"(p));
    return a;
}

#define MMA_F16(d, a0, a1, a2, a3, b0, b1)                                     \
    asm volatile(                                                              \
        "mma.sync.aligned.m16n8k16.row.col.f32.f16.f16.f32 "                   \
        "{%0,%1,%2,%3}, {%4,%5,%6,%7}, {%8,%9}, {%0,%1,%2,%3};"                \
        : "+f"(d[0]), "+f"(d[1]), "+f"(d[2]), "+f"(d[3])                       \
        : "r"(a0), "r"(a1), "r"(a2), "r"(a3), "r"(b0), "r"(b1))

#define CPA16(sa, gp)                                                          \
    asm volatile("cp.async.cg.shared.global [%0], [%1], 16;"                   \
                 :: "r"(sa), "l"(gp) : "memory")
#define CPA_COMMIT() asm volatile("cp.async.commit_group;" ::: "memory")
#define CPA_WAIT1()  asm volatile("cp.async.wait_group 1;" ::: "memory")
#define CPA_WAIT0()  asm volatile("cp.async.wait_group 0;" ::: "memory")
#define LDS64(v, a)                                                            \
    asm volatile("ld.shared.v2.u32 {%0,%1}, [%2];"                             \
                 : "=r"((v).x), "=r"((v).y) : "r"(a))

// ======================== prep: fp32 -> fp16 pair-permuted =================
// Group of 16 halves: pair j (elems 2j,2j+1) stored at slot ((j&3)<<1)+(j>>2)
__device__ __forceinline__ void prep16(const float* f, uint32_t* o) {
#pragma unroll
    for (int j = 0; j < 8; j++) {
        __half2 h = __floats2half2_rn(f[2 * j], f[2 * j + 1]);
        o[((j & 3) << 1) + (j >> 2)] = *(uint32_t*)&h;
    }
}

__global__ void __launch_bounds__(256)
prep_x_f2h(const float* __restrict__ in, __half* __restrict__ out) {
    size_t g = (size_t)blockIdx.x * 256 + threadIdx.x;   // group of 16
    float f[16];
#pragma unroll
    for (int q = 0; q < 4; q++)
        *(float4*)&f[4 * q] = ((const float4*)in)[4 * g + q];
    uint32_t o[8];
    prep16(f, o);
    ((uint4*)out)[2 * g]     = make_uint4(o[0], o[1], o[2], o[3]);
    ((uint4*)out)[2 * g + 1] = make_uint4(o[4], o[5], o[6], o[7]);
}

__global__ void __launch_bounds__(256)
prep_w_f2h(const float* __restrict__ w0, const float* __restrict__ w1,
           const float* __restrict__ w2, const float* __restrict__ w3,
           __half* __restrict__ out) {
    size_t g = (size_t)blockIdx.x * 256 + threadIdx.x;   // group of 16
    int wsel = (int)(g >> 14);                            // 16384 groups per W
    const float* src = wsel == 0 ? w0 : wsel == 1 ? w1 : wsel == 2 ? w2 : w3;
    size_t off = (g & 16383) * 16;
    float f[16];
#pragma unroll
    for (int q = 0; q < 4; q++)
        *(float4*)&f[4 * q] = ((const float4*)(src + off))[q];
    uint32_t o[8];
    prep16(f, o);
    ((uint4*)out)[2 * g]     = make_uint4(o[0], o[1], o[2], o[3]);
    ((uint4*)out)[2 * g + 1] = make_uint4(o[4], o[5], o[6], o[7]);
}

// ======================== GEMM (fp16 mma.sync, cp.async x3 stages) =========
// Block 128x128, BK=64 halves (128B/row), 128 threads = 4 warps (2Mx2N),
// warp tile 64x64. Stage = A(16KB)+B(16KB); 3 stages = 96KB; 2 CTAs/SM.
#define GSTAGE  32768
#define GSMEM   (3 * GSTAGE + 128)

__global__ void __launch_bounds__(128, 2)
gemm_f16(const __half* __restrict__ A, const __half* __restrict__ Wt,
         void* __restrict__ Cv, size_t c_stride,
         uint32_t perm_mask, uint32_t round_mask) {
    extern __shared__ char dsmem[];
    const uint32_t sb = (smem_u32(dsmem) + 127u) & ~127u;

    const int tid  = threadIdx.x;
    const int lane = tid & 31;
    const int wid  = tid >> 5;
    const int wm   = wid & 1;
    const int wn   = wid >> 1;
    const int c    = lane & 3;
    const int r8   = lane >> 2;

    const int nb   = blockIdx.x;
    const int wsel = nb >> 2;
    const int n0   = (nb & 3) * 128;
    const int m0   = blockIdx.y * 128;

    const __half* Aw = A + (size_t)m0 * 512;
    const __half* Bw = Wt + (size_t)wsel * WELEMS + (size_t)n0 * 512;

    float acc[4][8][4];
#pragma unroll
    for (int mt = 0; mt < 4; mt++)
#pragma unroll
        for (int nt = 0; nt < 8; nt++)
#pragma unroll
            for (int i = 0; i < 4; i++) acc[mt][nt][i] = 0.0f;

    auto load_stage = [&](int s, int kt) {
        const uint32_t stage = sb + s * GSTAGE;
#pragma unroll
        for (int i = 0; i < 16; i++) {
            const int cid = tid + i * 128;           // 0..2047 16B chunks
            const int isB = cid >> 10;
            const int r   = (cid >> 3) & 127;
            const int ch  = cid & 7;
            const uint32_t so =
                stage + isB * 16384 + r * 128 + (((ch ^ (r & 7)) << 4));
            const __half* gp =
                (isB ? Bw : Aw) + (size_t)r * 512 + kt * 64 + ch * 8;
            CPA16(so, gp);
        }
        CPA_COMMIT();
    };

    auto compute = [&](int s) {
        const uint32_t sA = sb + s * GSTAGE + (wm * 64 + r8) * 128 + 8 * (c & 1);
        const uint32_t sB = sb + s * GSTAGE + 16384 + wn * 8192 + r8 * 128 +
                            8 * (c & 1);
#pragma unroll
        for (int g = 0; g < 4; g++) {
            const uint32_t csw = (uint32_t)(((2 * g + (c >> 1)) ^ r8) << 4);
            uint2 lo, hi;
            unsigned a0[4], a1[4], a2[4], a3[4], b0[8], b1[8];
#pragma unroll
            for (int mt = 0; mt < 4; mt++) {
                LDS64(lo, sA + mt * 2048 + csw);
                LDS64(hi, sA + mt * 2048 + 1024 + csw);
                a0[mt] = lo.x; a2[mt] = lo.y; a1[mt] = hi.x; a3[mt] = hi.y;
            }
#pragma unroll
            for (int nt = 0; nt < 8; nt++) {
                LDS64(lo, sB + nt * 1024 + csw);
                b0[nt] = lo.x; b1[nt] = lo.y;
            }
#pragma unroll
            for (int mt = 0; mt < 4; mt++)
#pragma unroll
                for (int nt = 0; nt < 8; nt++)
                    MMA_F16(acc[mt][nt], a0[mt], a1[mt], a2[mt], a3[mt],
                            b0[nt], b1[nt]);
        }
    };

    load_stage(0, 0);
    load_stage(1, 1);

    int scur = 0, snext = 1, sload = 2;
#pragma unroll 1
    for (int kt = 0; kt < 8; kt++) {
        if (kt < 7) { CPA_WAIT1(); } else { CPA_WAIT0(); }
        __syncthreads();
        if (kt + 2 < 8) load_stage(sload, kt + 2);
        compute(scur);
        const int t = scur; scur = snext; snext = sload; sload = t;
    }

    // Epilogue: perm -> fp16 pair-permuted; rnd -> fp16 plain; else fp32.
    const bool perm = (perm_mask >> wsel) & 1u;
    const bool rnd  = (round_mask >> wsel) & 1u;
    if (perm || rnd) {
        __half* Ch = (__half*)Cv + (size_t)wsel * c_stride;
#pragma unroll
        for (int mt = 0; mt < 4; mt++) {
            const int row = m0 + wm * 64 + mt * 16 + r8;
#pragma unroll
            for (int nt = 0; nt < 8; nt++) {
                __half2 lo = __floats2half2_rn(acc[mt][nt][0], acc[mt][nt][1]);
                __half2 hi = __floats2half2_rn(acc[mt][nt][2], acc[mt][nt][3]);
                int off;
                if (perm)
                    off = n0 + wn * 64 + (nt >> 1) * 16 + 4 * c + 2 * (nt & 1);
                else
                    off = n0 + wn * 64 + nt * 8 + 2 * c;
                *(__half2*)&Ch[(size_t)row * 512 + off]       = lo;
                *(__half2*)&Ch[(size_t)(row + 8) * 512 + off] = hi;
            }
        }
    } else {
        float* Cf = (float*)Cv;
#pragma unroll
        for (int mt = 0; mt < 4; mt++) {
            const int row = m0 + wm * 64 + mt * 16 + r8;
#pragma unroll
            for (int nt = 0; nt < 8; nt++) {
                const int col = n0 + wn * 64 + nt * 8 + 2 * c;
                *(float2*)&Cf[(size_t)row * 512 + col] =
                    make_float2(acc[mt][nt][0], acc[mt][nt][1]);
                *(float2*)&Cf[(size_t)(row + 8) * 512 + col] =
                    make_float2(acc[mt][nt][2], acc[mt][nt][3]);
            }
        }
    }
}

// ======================== attention (fp16 mma.sync) ========================
// One block (128 threads) per (batch, head). Q,K arrive fp16 pair-permuted;
// V arrives plain fp16 and is transposed+permuted during staging.
// Row strides 40 / 72 halves keep every fragment LDS.64 at 2-phase optimal.
__global__ void __launch_bounds__(128, 7)
attn64_f16(const __half* __restrict__ Q, const __half* __restrict__ K,
           const __half* __restrict__ V, __half* __restrict__ At) {
    __shared__ union {
        struct { __half Q[64][40]; __half K[64][40]; } qk;
        __half P[4][16][72];
    } u;
    __shared__ __half Vt[32][72];

    const int tid  = threadIdx.x;
    const int lane = tid & 31;
    const int w    = tid >> 5;
    const int c    = lane & 3;
    const int r8   = lane >> 2;

    const int bh = blockIdx.x;
    const int b  = bh >> 4;
    const int h  = bh & 15;
    const size_t rbase = (size_t)b * SEQ * D_MODEL + h * DK;

    // Staging: thread = (row, half-of-row).
    const int lrow = tid >> 1;
    const int part = tid & 1;
    {
        const __half* qp = Q + rbase + (size_t)lrow * D_MODEL + part * 16;
        const __half* kp = K + rbase + (size_t)lrow * D_MODEL + part * 16;
        const __half* vp = V + rbase + (size_t)lrow * D_MODEL + part * 16;
        *(uint4*)&u.qk.Q[lrow][part * 16]     = ((const uint4*)qp)[0];
        *(uint4*)&u.qk.Q[lrow][part * 16 + 8] = ((const uint4*)qp)[1];
        *(uint4*)&u.qk.K[lrow][part * 16]     = ((const uint4*)kp)[0];
        *(uint4*)&u.qk.K[lrow][part * 16 + 8] = ((const uint4*)kp)[1];
        // V transpose + seq pair-permute.
        uint4 v0 = ((const uint4*)vp)[0], v1 = ((const uint4*)vp)[1];
        __half vh[16];
        *(uint4*)&vh[0] = v0;
        *(uint4*)&vh[8] = v1;
        const int p    = (lrow >> 1) & 7;
        const int slot = ((p & 3) << 1) + (p >> 2);
        const int ps   = (lrow & ~15) + slot * 2 + (lrow & 1);
#pragma unroll
        for (int j = 0; j < 16; j++) Vt[part * 16 + j][ps] = vh[j];
    }
    __syncthreads();

    // ---- S = Q K^T  (M=16/warp, N=64, K=32 -> 2 k16 groups) ----
    const uint32_t sQ = smem_u32(&u.qk.Q[0][0]);
    const uint32_t sK = smem_u32(&u.qk.K[0][0]);
    float s[8][4];
#pragma unroll
    for (int nt = 0; nt < 8; nt++)
#pragma unroll
        for (int i = 0; i < 4; i++) s[nt][i] = 0.0f;

#pragma unroll
    for (int g = 0; g < 2; g++) {
        const uint32_t ko = g * 32 + 8 * c;
        uint2 alo, ahi;
        LDS64(alo, sQ + (w * 16 + r8) * 80 + ko);
        LDS64(ahi, sQ + (w * 16 + 8 + r8) * 80 + ko);
#pragma unroll
        for (int nt = 0; nt < 8; nt++) {
            uint2 bb;
            LDS64(bb, sK + (nt * 8 + r8) * 80 + ko);
            MMA_F16(s[nt], alo.x, ahi.x, alo.y, ahi.y, bb.x, bb.y);
        }
    }

    // ---- softmax ----
    const float scale = 0.17677669529663687f;  // 1/sqrt(32)
#pragma unroll
    for (int nt = 0; nt < 8; nt++)
#pragma unroll
        for (int i = 0; i < 4; i++) s[nt][i] *= scale;

    float m1 = -1e30f, m2 = -1e30f;
#pragma unroll
    for (int nt = 0; nt < 8; nt++) {
        m1 = fmaxf(m1, fmaxf(s[nt][0], s[nt][1]));
        m2 = fmaxf(m2, fmaxf(s[nt][2], s[nt][3]));
    }
    m1 = fmaxf(m1, __shfl_xor_sync(0xffffffffu, m1, 1));
    m1 = fmaxf(m1, __shfl_xor_sync(0xffffffffu, m1, 2));
    m2 = fmaxf(m2, __shfl_xor_sync(0xffffffffu, m2, 1));
    m2 = fmaxf(m2, __shfl_xor_sync(0xffffffffu, m2, 2));

    float sum1 = 0.0f, sum2 = 0.0f;
#pragma unroll
    for (int nt = 0; nt < 8; nt++) {
        s[nt][0] = __expf(s[nt][0] - m1);
        s[nt][1] = __expf(s[nt][1] - m1);
        s[nt][2] = __expf(s[nt][2] - m2);
        s[nt][3] = __expf(s[nt][3] - m2);
        sum1 += s[nt][0] + s[nt][1];
        sum2 += s[nt][2] + s[nt][3];
    }
    sum1 += __shfl_xor_sync(0xffffffffu, sum1, 1);
    sum1 += __shfl_xor_sync(0xffffffffu, sum1, 2);
    sum2 += __shfl_xor_sync(0xffffffffu, sum2, 1);
    sum2 += __shfl_xor_sync(0xffffffffu, sum2, 2);
    const float inv1 = 1.0f / sum1;
    const float inv2 = 1.0f / sum2;

    // All warps must be done reading Qs/Ks before P overlays them.
    __syncthreads();

    // Store P fp16, pair-permuted along seq. Pair (cols 2c,2c+1) of n8-tile
    // nt is pair j=(nt&1)*4+c of its 16-group -> slot 2c+(nt&1).
#pragma unroll
    for (int nt = 0; nt < 8; nt++) {
        const int off = (nt >> 1) * 16 + 4 * c + 2 * (nt & 1);
        __half2 lo = __floats2half2_rn(s[nt][0] * inv1, s[nt][1] * inv1);
        __half2 hi = __floats2half2_rn(s[nt][2] * inv2, s[nt][3] * inv2);
        *(__half2*)&u.P[w][r8][off]     = lo;
        *(__half2*)&u.P[w][r8 + 8][off] = hi;
    }
    __syncwarp();

    // ---- O = P V  (M=16/warp, N=32, K=64 -> 4 k16 groups) ----
    const uint32_t pA = smem_u32(&u.P[w][0][0]);
    const uint32_t pV = smem_u32(&Vt[0][0]);
    float o[4][4];
#pragma unroll
    for (int nt = 0; nt < 4; nt++)
#pragma unroll
        for (int i = 0; i < 4; i++) o[nt][i] = 0.0f;

#pragma unroll
    for (int g = 0; g < 4; g++) {
        const uint32_t ko = g * 32 + 8 * c;
        uint2 alo, ahi;
        LDS64(alo, pA + r8 * 144 + ko);
        LDS64(ahi, pA + (r8 + 8) * 144 + ko);
#pragma unroll
        for (int nt = 0; nt < 4; nt++) {
            uint2 bb;
            LDS64(bb, pV + (nt * 8 + r8) * 144 + ko);
            MMA_F16(o[nt], alo.x, ahi.x, alo.y, ahi.y, bb.x, bb.y);
        }
    }

    // Epilogue: fp16, pair-permuted (Wo-GEMM input layout).
    const int row = b * SEQ + w * 16 + r8;
#pragma unroll
    for (int nt = 0; nt < 4; nt++) {
        const int off = h * DK + (nt >> 1) * 16 + 4 * c + 2 * (nt & 1);
        *(__half2*)&At[(size_t)row * 512 + off] =
            __floats2half2_rn(o[nt][0], o[nt][1]);
        *(__half2*)&At[(size_t)(row + 8) * 512 + off] =
            __floats2half2_rn(o[nt][2], o[nt][3]);
    }
}

// ======================== launch ===========================================
extern "C" void kernel_launch(void* const* d_in, const int* in_sizes, int n_in,
                              void* d_out, int out_size) {
    (void)in_sizes; (void)n_in; (void)out_size;
    const float* x  = (const float*)d_in[0];
    const float* Wq = (const float*)d_in[1];
    const float* Wk = (const float*)d_in[2];
    const float* Wv = (const float*)d_in[3];
    const float* Wo = (const float*)d_in[4];
    float* out = (float*)d_out;

    void *pxh, *pwh, *pqkv, *pat;
    cudaGetSymbolAddress(&pxh, g_xh);
    cudaGetSymbolAddress(&pwh, g_wh);
    cudaGetSymbolAddress(&pqkv, g_qkvh);
    cudaGetSymbolAddress(&pat, g_ath);

    cudaFuncSetAttribute(gemm_f16,
                         cudaFuncAttributeMaxDynamicSharedMemorySize, GSMEM);

    prep_w_f2h<<<256, 256>>>(Wq, Wk, Wv, Wo, (__half*)pwh);
    prep_x_f2h<<<16384, 256>>>(x, (__half*)pxh);

    // Fused Q,K,V projections: Q,K perm fp16; V plain fp16.
    gemm_f16<<<dim3(12, M_ROWS / 128), 128, GSMEM>>>(
        (const __half*)pxh, (const __half*)pwh, pqkv, MS,
        /*perm_mask=*/0b011u, /*round_mask=*/0b100u);

    const __half* q = (const __half*)pqkv;
    const __half* k = q + MS;
    const __half* v = k + MS;
    attn64_f16<<<M_ROWS / SEQ * NUM_HEADS, 128>>>(q, k, v, (__half*)pat);

    // Output projection: plain fp32 output.
    gemm_f16<<<dim3(4, M_ROWS / 128), 128, GSMEM>>>(
        (const __half*)pat, (const __half*)pwh + 3 * WELEMS, out, 0, 0u, 0u);
}

// round 9
// speedup vs baseline: 1.8730x; 1.0274x over previous
#include <cuda_runtime.h>
#include <cuda_fp16.h>
#include <cstdint>

// ---------------------------------------------------------------------------
// x:(2048,64,512) fp32, Wq/Wk/Wv/Wo:(512,512) fp32
// out = SDPA(x@WqT, x@WkT, x@WvT) @ WoT    H=16, dk=32, S=64
//
// R9: fp16 mma.sync pipeline (R8) + attention register-retimed PV:
// the QK^T output fragment IS the PV A-operand fragment, so P never
// goes through SMEM (removes 16 STS.32 + 8 LDS.64 per thread + 1 barrier).
// Bit-identical numerics to R8.
// ---------------------------------------------------------------------------

#define D_MODEL   512
#define M_ROWS    131072
#define NUM_HEADS 16
#define SEQ       64
#define DK        32

#define MS        ((size_t)M_ROWS * D_MODEL)
#define WELEMS    ((size_t)D_MODEL * D_MODEL)

__device__ __half g_xh[MS];            // x, fp16, pair-permuted along k
__device__ __half g_wh[4 * WELEMS];    // Wq,Wk,Wv,Wo fp16, pair-permuted
__device__ __half g_qkvh[3 * MS];      // q(perm), k(perm), v(plain)
__device__ __half g_ath[MS];           // attn out fp16, pair-permuted

// ======================== helpers ==========================================
__device__ __forceinline__ uint32_t smem_u32(const void* p) {
    uint32_t a;
    asm("{ .reg .u64 t; cvta.to.shared.u64 t, %1; cvt.u32.u64 %0, t; }"
        : "=r"(a) : "l"(p));
    return a;
}

#define MMA_F16(d, a0, a1, a2, a3, b0, b1)                                     \
    asm volatile(                                                              \
        "mma.sync.aligned.m16n8k16.row.col.f32.f16.f16.f32 "                   \
        "{%0,%1,%2,%3}, {%4,%5,%6,%7}, {%8,%9}, {%0,%1,%2,%3};"                \
        : "+f"(d[0]), "+f"(d[1]), "+f"(d[2]), "+f"(d[3])                       \
        : "r"(a0), "r"(a1), "r"(a2), "r"(a3), "r"(b0), "r"(b1))

#define CPA16(sa, gp)                                                          \
    asm volatile("cp.async.cg.shared.global [%0], [%1], 16;"                   \
                 :: "r"(sa), "l"(gp) : "memory")
#define CPA_COMMIT() asm volatile("cp.async.commit_group;" ::: "memory")
#define CPA_WAIT1()  asm volatile("cp.async.wait_group 1;" ::: "memory")
#define CPA_WAIT0()  asm volatile("cp.async.wait_group 0;" ::: "memory")
#define LDS64(v, a)                                                            \
    asm volatile("ld.shared.v2.u32 {%0,%1}, [%2];"                             \
                 : "=r"((v).x), "=r"((v).y) : "r"(a))

__device__ __forceinline__ uint32_t packh2(float a, float b) {
    __half2 h = __floats2half2_rn(a, b);
    return *(uint32_t*)&h;
}

// ======================== prep: fp32 -> fp16 pair-permuted =================
// Group of 16 halves: pair j (elems 2j,2j+1) stored at slot ((j&3)<<1)+(j>>2)
__device__ __forceinline__ void prep16(const float* f, uint32_t* o) {
#pragma unroll
    for (int j = 0; j < 8; j++)
        o[((j & 3) << 1) + (j >> 2)] = packh2(f[2 * j], f[2 * j + 1]);
}

__global__ void __launch_bounds__(256)
prep_x_f2h(const float* __restrict__ in, __half* __restrict__ out) {
    size_t g = (size_t)blockIdx.x * 256 + threadIdx.x;   // group of 16
    float f[16];
#pragma unroll
    for (int q = 0; q < 4; q++)
        *(float4*)&f[4 * q] = ((const float4*)in)[4 * g + q];
    uint32_t o[8];
    prep16(f, o);
    ((uint4*)out)[2 * g]     = make_uint4(o[0], o[1], o[2], o[3]);
    ((uint4*)out)[2 * g + 1] = make_uint4(o[4], o[5], o[6], o[7]);
}

__global__ void __launch_bounds__(256)
prep_w_f2h(const float* __restrict__ w0, const float* __restrict__ w1,
           const float* __restrict__ w2, const float* __restrict__ w3,
           __half* __restrict__ out) {
    size_t g = (size_t)blockIdx.x * 256 + threadIdx.x;   // group of 16
    int wsel = (int)(g >> 14);                            // 16384 groups per W
    const float* src = wsel == 0 ? w0 : wsel == 1 ? w1 : wsel == 2 ? w2 : w3;
    size_t off = (g & 16383) * 16;
    float f[16];
#pragma unroll
    for (int q = 0; q < 4; q++)
        *(float4*)&f[4 * q] = ((const float4*)(src + off))[q];
    uint32_t o[8];
    prep16(f, o);
    ((uint4*)out)[2 * g]     = make_uint4(o[0], o[1], o[2], o[3]);
    ((uint4*)out)[2 * g + 1] = make_uint4(o[4], o[5], o[6], o[7]);
}

// ======================== GEMM (fp16 mma.sync, cp.async x3 stages) =========
// Block 128x128, BK=64 halves (128B/row), 128 threads = 4 warps (2Mx2N),
// warp tile 64x64. Stage = A(16KB)+B(16KB); 3 stages = 96KB; 2 CTAs/SM.
#define GSTAGE  32768
#define GSMEM   (3 * GSTAGE + 128)

__global__ void __launch_bounds__(128, 2)
gemm_f16(const __half* __restrict__ A, const __half* __restrict__ Wt,
         void* __restrict__ Cv, size_t c_stride,
         uint32_t perm_mask, uint32_t round_mask) {
    extern __shared__ char dsmem[];
    const uint32_t sb = (smem_u32(dsmem) + 127u) & ~127u;

    const int tid  = threadIdx.x;
    const int lane = tid & 31;
    const int wid  = tid >> 5;
    const int wm   = wid & 1;
    const int wn   = wid >> 1;
    const int c    = lane & 3;
    const int r8   = lane >> 2;

    const int nb   = blockIdx.x;
    const int wsel = nb >> 2;
    const int n0   = (nb & 3) * 128;
    const int m0   = blockIdx.y * 128;

    const __half* Aw = A + (size_t)m0 * 512;
    const __half* Bw = Wt + (size_t)wsel * WELEMS + (size_t)n0 * 512;

    float acc[4][8][4];
#pragma unroll
    for (int mt = 0; mt < 4; mt++)
#pragma unroll
        for (int nt = 0; nt < 8; nt++)
#pragma unroll
            for (int i = 0; i < 4; i++) acc[mt][nt][i] = 0.0f;

    auto load_stage = [&](int s, int kt) {
        const uint32_t stage = sb + s * GSTAGE;
#pragma unroll
        for (int i = 0; i < 16; i++) {
            const int cid = tid + i * 128;           // 0..2047 16B chunks
            const int isB = cid >> 10;
            const int r   = (cid >> 3) & 127;
            const int ch  = cid & 7;
            const uint32_t so =
                stage + isB * 16384 + r * 128 + (((ch ^ (r & 7)) << 4));
            const __half* gp =
                (isB ? Bw : Aw) + (size_t)r * 512 + kt * 64 + ch * 8;
            CPA16(so, gp);
        }
        CPA_COMMIT();
    };

    auto compute = [&](int s) {
        const uint32_t sA = sb + s * GSTAGE + (wm * 64 + r8) * 128 + 8 * (c & 1);
        const uint32_t sB = sb + s * GSTAGE + 16384 + wn * 8192 + r8 * 128 +
                            8 * (c & 1);
#pragma unroll
        for (int g = 0; g < 4; g++) {
            const uint32_t csw = (uint32_t)(((2 * g + (c >> 1)) ^ r8) << 4);
            uint2 lo, hi;
            unsigned a0[4], a1[4], a2[4], a3[4], b0[8], b1[8];
#pragma unroll
            for (int mt = 0; mt < 4; mt++) {
                LDS64(lo, sA + mt * 2048 + csw);
                LDS64(hi, sA + mt * 2048 + 1024 + csw);
                a0[mt] = lo.x; a2[mt] = lo.y; a1[mt] = hi.x; a3[mt] = hi.y;
            }
#pragma unroll
            for (int nt = 0; nt < 8; nt++) {
                LDS64(lo, sB + nt * 1024 + csw);
                b0[nt] = lo.x; b1[nt] = lo.y;
            }
#pragma unroll
            for (int mt = 0; mt < 4; mt++)
#pragma unroll
                for (int nt = 0; nt < 8; nt++)
                    MMA_F16(acc[mt][nt], a0[mt], a1[mt], a2[mt], a3[mt],
                            b0[nt], b1[nt]);
        }
    };

    load_stage(0, 0);
    load_stage(1, 1);

    int scur = 0, snext = 1, sload = 2;
#pragma unroll 1
    for (int kt = 0; kt < 8; kt++) {
        if (kt < 7) { CPA_WAIT1(); } else { CPA_WAIT0(); }
        __syncthreads();
        if (kt + 2 < 8) load_stage(sload, kt + 2);
        compute(scur);
        const int t = scur; scur = snext; snext = sload; sload = t;
    }

    // Epilogue: perm -> fp16 pair-permuted; rnd -> fp16 plain; else fp32.
    const bool perm = (perm_mask >> wsel) & 1u;
    const bool rnd  = (round_mask >> wsel) & 1u;
    if (perm || rnd) {
        __half* Ch = (__half*)Cv + (size_t)wsel * c_stride;
#pragma unroll
        for (int mt = 0; mt < 4; mt++) {
            const int row = m0 + wm * 64 + mt * 16 + r8;
#pragma unroll
            for (int nt = 0; nt < 8; nt++) {
                __half2 lo = __floats2half2_rn(acc[mt][nt][0], acc[mt][nt][1]);
                __half2 hi = __floats2half2_rn(acc[mt][nt][2], acc[mt][nt][3]);
                int off;
                if (perm)
                    off = n0 + wn * 64 + (nt >> 1) * 16 + 4 * c + 2 * (nt & 1);
                else
                    off = n0 + wn * 64 + nt * 8 + 2 * c;
                *(__half2*)&Ch[(size_t)row * 512 + off]       = lo;
                *(__half2*)&Ch[(size_t)(row + 8) * 512 + off] = hi;
            }
        }
    } else {
        float* Cf = (float*)Cv;
#pragma unroll
        for (int mt = 0; mt < 4; mt++) {
            const int row = m0 + wm * 64 + mt * 16 + r8;
#pragma unroll
            for (int nt = 0; nt < 8; nt++) {
                const int col = n0 + wn * 64 + nt * 8 + 2 * c;
                *(float2*)&Cf[(size_t)row * 512 + col] =
                    make_float2(acc[mt][nt][0], acc[mt][nt][1]);
                *(float2*)&Cf[(size_t)(row + 8) * 512 + col] =
                    make_float2(acc[mt][nt][2], acc[mt][nt][3]);
            }
        }
    }
}

// ======================== attention (fp16 mma.sync) ========================
// One block (128 threads) per (batch, head). Q,K arrive fp16 pair-permuted;
// V plain fp16, transposed+pair-permuted during staging. P stays in
// registers: the S-fragment IS the PV A-fragment.
__global__ void __launch_bounds__(128, 8)
attn64_f16(const __half* __restrict__ Q, const __half* __restrict__ K,
           const __half* __restrict__ V, __half* __restrict__ At) {
    __shared__ __half Qs[64][40];
    __shared__ __half Ks[64][40];
    __shared__ __half Vt[32][72];

    const int tid  = threadIdx.x;
    const int lane = tid & 31;
    const int w    = tid >> 5;
    const int c    = lane & 3;
    const int r8   = lane >> 2;

    const int bh = blockIdx.x;
    const int b  = bh >> 4;
    const int h  = bh & 15;
    const size_t rbase = (size_t)b * SEQ * D_MODEL + h * DK;

    // Staging: thread = (row, half-of-row).
    const int lrow = tid >> 1;
    const int part = tid & 1;
    {
        const __half* qp = Q + rbase + (size_t)lrow * D_MODEL + part * 16;
        const __half* kp = K + rbase + (size_t)lrow * D_MODEL + part * 16;
        const __half* vp = V + rbase + (size_t)lrow * D_MODEL + part * 16;
        *(uint4*)&Qs[lrow][part * 16]     = ((const uint4*)qp)[0];
        *(uint4*)&Qs[lrow][part * 16 + 8] = ((const uint4*)qp)[1];
        *(uint4*)&Ks[lrow][part * 16]     = ((const uint4*)kp)[0];
        *(uint4*)&Ks[lrow][part * 16 + 8] = ((const uint4*)kp)[1];
        // V transpose + seq pair-permute (pairs (j, j+4) adjacent).
        uint4 v0 = ((const uint4*)vp)[0], v1 = ((const uint4*)vp)[1];
        __half vh[16];
        *(uint4*)&vh[0] = v0;
        *(uint4*)&vh[8] = v1;
        const int p    = (lrow >> 1) & 7;
        const int slot = ((p & 3) << 1) + (p >> 2);
        const int ps   = (lrow & ~15) + slot * 2 + (lrow & 1);
#pragma unroll
        for (int j = 0; j < 16; j++) Vt[part * 16 + j][ps] = vh[j];
    }
    __syncthreads();

    // ---- S = Q K^T  (M=16/warp, N=64, K=32 -> 2 k16 groups) ----
    const uint32_t sQ = smem_u32(&Qs[0][0]);
    const uint32_t sK = smem_u32(&Ks[0][0]);
    float s[8][4];
#pragma unroll
    for (int nt = 0; nt < 8; nt++)
#pragma unroll
        for (int i = 0; i < 4; i++) s[nt][i] = 0.0f;

#pragma unroll
    for (int g = 0; g < 2; g++) {
        const uint32_t ko = g * 32 + 8 * c;
        uint2 alo, ahi;
        LDS64(alo, sQ + (w * 16 + r8) * 80 + ko);
        LDS64(ahi, sQ + (w * 16 + 8 + r8) * 80 + ko);
#pragma unroll
        for (int nt = 0; nt < 8; nt++) {
            uint2 bb;
            LDS64(bb, sK + (nt * 8 + r8) * 80 + ko);
            MMA_F16(s[nt], alo.x, ahi.x, alo.y, ahi.y, bb.x, bb.y);
        }
    }

    // ---- softmax ----
    const float scale = 0.17677669529663687f;  // 1/sqrt(32)
#pragma unroll
    for (int nt = 0; nt < 8; nt++)
#pragma unroll
        for (int i = 0; i < 4; i++) s[nt][i] *= scale;

    float m1 = -1e30f, m2 = -1e30f;
#pragma unroll
    for (int nt = 0; nt < 8; nt++) {
        m1 = fmaxf(m1, fmaxf(s[nt][0], s[nt][1]));
        m2 = fmaxf(m2, fmaxf(s[nt][2], s[nt][3]));
    }
    m1 = fmaxf(m1, __shfl_xor_sync(0xffffffffu, m1, 1));
    m1 = fmaxf(m1, __shfl_xor_sync(0xffffffffu, m1, 2));
    m2 = fmaxf(m2, __shfl_xor_sync(0xffffffffu, m2, 1));
    m2 = fmaxf(m2, __shfl_xor_sync(0xffffffffu, m2, 2));

    float sum1 = 0.0f, sum2 = 0.0f;
#pragma unroll
    for (int nt = 0; nt < 8; nt++) {
        s[nt][0] = __expf(s[nt][0] - m1);
        s[nt][1] = __expf(s[nt][1] - m1);
        s[nt][2] = __expf(s[nt][2] - m2);
        s[nt][3] = __expf(s[nt][3] - m2);
        sum1 += s[nt][0] + s[nt][1];
        sum2 += s[nt][2] + s[nt][3];
    }
    sum1 += __shfl_xor_sync(0xffffffffu, sum1, 1);
    sum1 += __shfl_xor_sync(0xffffffffu, sum1, 2);
    sum2 += __shfl_xor_sync(0xffffffffu, sum2, 1);
    sum2 += __shfl_xor_sync(0xffffffffu, sum2, 2);
    const float inv1 = 1.0f / sum1;
    const float inv2 = 1.0f / sum2;

    // ---- O = P V: P comes straight from registers. For k16-group g,
    // A-fragment = (a0,a1) from s[2g], (a2,a3) from s[2g+1]. ----
    const uint32_t pV = smem_u32(&Vt[0][0]);
    float o[4][4];
#pragma unroll
    for (int nt = 0; nt < 4; nt++)
#pragma unroll
        for (int i = 0; i < 4; i++) o[nt][i] = 0.0f;

#pragma unroll
    for (int g = 0; g < 4; g++) {
        const uint32_t a0 = packh2(s[2 * g][0] * inv1, s[2 * g][1] * inv1);
        const uint32_t a1 = packh2(s[2 * g][2] * inv2, s[2 * g][3] * inv2);
        const uint32_t a2 = packh2(s[2 * g + 1][0] * inv1, s[2 * g + 1][1] * inv1);
        const uint32_t a3 = packh2(s[2 * g + 1][2] * inv2, s[2 * g + 1][3] * inv2);
        const uint32_t ko = g * 32 + 8 * c;
#pragma unroll
        for (int nt = 0; nt < 4; nt++) {
            uint2 bb;
            LDS64(bb, pV + (nt * 8 + r8) * 144 + ko);
            MMA_F16(o[nt], a0, a1, a2, a3, bb.x, bb.y);
        }
    }

    // Epilogue: fp16, pair-permuted (Wo-GEMM input layout).
    const int row = b * SEQ + w * 16 + r8;
#pragma unroll
    for (int nt = 0; nt < 4; nt++) {
        const int off = h * DK + (nt >> 1) * 16 + 4 * c + 2 * (nt & 1);
        *(__half2*)&At[(size_t)row * 512 + off] =
            __floats2half2_rn(o[nt][0], o[nt][1]);
        *(__half2*)&At[(size_t)(row + 8) * 512 + off] =
            __floats2half2_rn(o[nt][2], o[nt][3]);
    }
}

// ======================== launch ===========================================
extern "C" void kernel_launch(void* const* d_in, const int* in_sizes, int n_in,
                              void* d_out, int out_size) {
    (void)in_sizes; (void)n_in; (void)out_size;
    const float* x  = (const float*)d_in[0];
    const float* Wq = (const float*)d_in[1];
    const float* Wk = (const float*)d_in[2];
    const float* Wv = (const float*)d_in[3];
    const float* Wo = (const float*)d_in[4];
    float* out = (float*)d_out;

    void *pxh, *pwh, *pqkv, *pat;
    cudaGetSymbolAddress(&pxh, g_xh);
    cudaGetSymbolAddress(&pwh, g_wh);
    cudaGetSymbolAddress(&pqkv, g_qkvh);
    cudaGetSymbolAddress(&pat, g_ath);

    cudaFuncSetAttribute(gemm_f16,
                         cudaFuncAttributeMaxDynamicSharedMemorySize, GSMEM);

    prep_w_f2h<<<256, 256>>>(Wq, Wk, Wv, Wo, (__half*)pwh);
    prep_x_f2h<<<16384, 256>>>(x, (__half*)pxh);

    // Fused Q,K,V projections: Q,K perm fp16; V plain fp16.
    gemm_f16<<<dim3(12, M_ROWS / 128), 128, GSMEM>>>(
        (const __half*)pxh, (const __half*)pwh, pqkv, MS,
        /*perm_mask=*/0b011u, /*round_mask=*/0b100u);

    const __half* q = (const __half*)pqkv;
    const __half* k = q + MS;
    const __half* v = k + MS;
    attn64_f16<<<M_ROWS / SEQ * NUM_HEADS, 128>>>(q, k, v, (__half*)pat);

    // Output projection: plain fp32 output.
    gemm_f16<<<dim3(4, M_ROWS / 128), 128, GSMEM>>>(
        (const __half*)pat, (const __half*)pwh + 3 * WELEMS, out, 0, 0u, 0u);
}

// round 10
// speedup vs baseline: 1.9463x; 1.0391x over previous
#include <cuda_runtime.h>
#include <cuda_fp16.h>
#include <cstdint>

// ---------------------------------------------------------------------------
// x:(2048,64,512) fp32, Wq/Wk/Wv/Wo:(512,512) fp32
// out = SDPA(x@WqT, x@WkT, x@WvT) @ WoT    H=16, dk=32, S=64
//
// R10: attention fragment loads via ldmatrix (x4 / x4.trans). V is staged as
// plain rows (no scatter transpose); Q/K no longer pair-permuted (QKV GEMM
// writes plain fp16). P stays in registers (S-fragment == PV A-fragment).
// GEMM mainloop unchanged (at the legacy HMMA issue floor).
// ---------------------------------------------------------------------------

#define D_MODEL   512
#define M_ROWS    131072
#define NUM_HEADS 16
#define SEQ       64
#define DK        32

#define MS        ((size_t)M_ROWS * D_MODEL)
#define WELEMS    ((size_t)D_MODEL * D_MODEL)

__device__ __half g_xh[MS];            // x, fp16, pair-permuted along k
__device__ __half g_wh[4 * WELEMS];    // Wq,Wk,Wv,Wo fp16, pair-permuted
__device__ __half g_qkvh[3 * MS];      // q, k, v (all plain fp16)
__device__ __half g_ath[MS];           // attn out fp16, pair-permuted

// ======================== helpers ==========================================
__device__ __forceinline__ uint32_t smem_u32(const void* p) {
    uint32_t a;
    asm("{ .reg .u64 t; cvta.to.shared.u64 t, %1; cvt.u32.u64 %0, t; }"
        : "=r"(a) : "l"(p));
    return a;
}

#define MMA_F16(d, a0, a1, a2, a3, b0, b1)                                     \
    asm volatile(                                                              \
        "mma.sync.aligned.m16n8k16.row.col.f32.f16.f16.f32 "                   \
        "{%0,%1,%2,%3}, {%4,%5,%6,%7}, {%8,%9}, {%0,%1,%2,%3};"                \
        : "+f"(d[0]), "+f"(d[1]), "+f"(d[2]), "+f"(d[3])                       \
        : "r"(a0), "r"(a1), "r"(a2), "r"(a3), "r"(b0), "r"(b1))

#define LDSM4(r0, r1, r2, r3, a)                                               \
    asm volatile("ldmatrix.sync.aligned.m8n8.x4.shared.b16 "                   \
                 "{%0,%1,%2,%3}, [%4];"                                        \
                 : "=r"(r0), "=r"(r1), "=r"(r2), "=r"(r3) : "r"(a))
#define LDSM4T(r0, r1, r2, r3, a)                                              \
    asm volatile("ldmatrix.sync.aligned.m8n8.x4.trans.shared.b16 "             \
                 "{%0,%1,%2,%3}, [%4];"                                        \
                 : "=r"(r0), "=r"(r1), "=r"(r2), "=r"(r3) : "r"(a))

#define CPA16(sa, gp)                                                          \
    asm volatile("cp.async.cg.shared.global [%0], [%1], 16;"                   \
                 :: "r"(sa), "l"(gp) : "memory")
#define CPA_COMMIT() asm volatile("cp.async.commit_group;" ::: "memory")
#define CPA_WAIT1()  asm volatile("cp.async.wait_group 1;" ::: "memory")
#define CPA_WAIT0()  asm volatile("cp.async.wait_group 0;" ::: "memory")
#define LDS64(v, a)                                                            \
    asm volatile("ld.shared.v2.u32 {%0,%1}, [%2];"                             \
                 : "=r"((v).x), "=r"((v).y) : "r"(a))

__device__ __forceinline__ uint32_t packh2(float a, float b) {
    __half2 h = __floats2half2_rn(a, b);
    return *(uint32_t*)&h;
}

// ======================== prep: fp32 -> fp16 pair-permuted =================
// (feeds the GEMM A/B LDS64 fragment path; unchanged)
__device__ __forceinline__ void prep16(const float* f, uint32_t* o) {
#pragma unroll
    for (int j = 0; j < 8; j++)
        o[((j & 3) << 1) + (j >> 2)] = packh2(f[2 * j], f[2 * j + 1]);
}

__global__ void __launch_bounds__(256)
prep_x_f2h(const float* __restrict__ in, __half* __restrict__ out) {
    size_t g = (size_t)blockIdx.x * 256 + threadIdx.x;   // group of 16
    float f[16];
#pragma unroll
    for (int q = 0; q < 4; q++)
        *(float4*)&f[4 * q] = ((const float4*)in)[4 * g + q];
    uint32_t o[8];
    prep16(f, o);
    ((uint4*)out)[2 * g]     = make_uint4(o[0], o[1], o[2], o[3]);
    ((uint4*)out)[2 * g + 1] = make_uint4(o[4], o[5], o[6], o[7]);
}

__global__ void __launch_bounds__(256)
prep_w_f2h(const float* __restrict__ w0, const float* __restrict__ w1,
           const float* __restrict__ w2, const float* __restrict__ w3,
           __half* __restrict__ out) {
    size_t g = (size_t)blockIdx.x * 256 + threadIdx.x;   // group of 16
    int wsel = (int)(g >> 14);                            // 16384 groups per W
    const float* src = wsel == 0 ? w0 : wsel == 1 ? w1 : wsel == 2 ? w2 : w3;
    size_t off = (g & 16383) * 16;
    float f[16];
#pragma unroll
    for (int q = 0; q < 4; q++)
        *(float4*)&f[4 * q] = ((const float4*)(src + off))[q];
    uint32_t o[8];
    prep16(f, o);
    ((uint4*)out)[2 * g]     = make_uint4(o[0], o[1], o[2], o[3]);
    ((uint4*)out)[2 * g + 1] = make_uint4(o[4], o[5], o[6], o[7]);
}

// ======================== GEMM (fp16 mma.sync, cp.async x3 stages) =========
// Block 128x128, BK=64 halves (128B/row), 128 threads = 4 warps (2Mx2N),
// warp tile 64x64. Stage = A(16KB)+B(16KB); 3 stages = 96KB; 2 CTAs/SM.
#define GSTAGE  32768
#define GSMEM   (3 * GSTAGE + 128)

__global__ void __launch_bounds__(128, 2)
gemm_f16(const __half* __restrict__ A, const __half* __restrict__ Wt,
         void* __restrict__ Cv, size_t c_stride, uint32_t round_mask) {
    extern __shared__ char dsmem[];
    const uint32_t sb = (smem_u32(dsmem) + 127u) & ~127u;

    const int tid  = threadIdx.x;
    const int lane = tid & 31;
    const int wid  = tid >> 5;
    const int wm   = wid & 1;
    const int wn   = wid >> 1;
    const int c    = lane & 3;
    const int r8   = lane >> 2;

    const int nb   = blockIdx.x;
    const int wsel = nb >> 2;
    const int n0   = (nb & 3) * 128;
    const int m0   = blockIdx.y * 128;

    const __half* Aw = A + (size_t)m0 * 512;
    const __half* Bw = Wt + (size_t)wsel * WELEMS + (size_t)n0 * 512;

    float acc[4][8][4];
#pragma unroll
    for (int mt = 0; mt < 4; mt++)
#pragma unroll
        for (int nt = 0; nt < 8; nt++)
#pragma unroll
            for (int i = 0; i < 4; i++) acc[mt][nt][i] = 0.0f;

    auto load_stage = [&](int s, int kt) {
        const uint32_t stage = sb + s * GSTAGE;
#pragma unroll
        for (int i = 0; i < 16; i++) {
            const int cid = tid + i * 128;           // 0..2047 16B chunks
            const int isB = cid >> 10;
            const int r   = (cid >> 3) & 127;
            const int ch  = cid & 7;
            const uint32_t so =
                stage + isB * 16384 + r * 128 + (((ch ^ (r & 7)) << 4));
            const __half* gp =
                (isB ? Bw : Aw) + (size_t)r * 512 + kt * 64 + ch * 8;
            CPA16(so, gp);
        }
        CPA_COMMIT();
    };

    auto compute = [&](int s) {
        const uint32_t sA = sb + s * GSTAGE + (wm * 64 + r8) * 128 + 8 * (c & 1);
        const uint32_t sB = sb + s * GSTAGE + 16384 + wn * 8192 + r8 * 128 +
                            8 * (c & 1);
#pragma unroll
        for (int g = 0; g < 4; g++) {
            const uint32_t csw = (uint32_t)(((2 * g + (c >> 1)) ^ r8) << 4);
            uint2 lo, hi;
            unsigned a0[4], a1[4], a2[4], a3[4], b0[8], b1[8];
#pragma unroll
            for (int mt = 0; mt < 4; mt++) {
                LDS64(lo, sA + mt * 2048 + csw);
                LDS64(hi, sA + mt * 2048 + 1024 + csw);
                a0[mt] = lo.x; a2[mt] = lo.y; a1[mt] = hi.x; a3[mt] = hi.y;
            }
#pragma unroll
            for (int nt = 0; nt < 8; nt++) {
                LDS64(lo, sB + nt * 1024 + csw);
                b0[nt] = lo.x; b1[nt] = lo.y;
            }
#pragma unroll
            for (int mt = 0; mt < 4; mt++)
#pragma unroll
                for (int nt = 0; nt < 8; nt++)
                    MMA_F16(acc[mt][nt], a0[mt], a1[mt], a2[mt], a3[mt],
                            b0[nt], b1[nt]);
        }
    };

    load_stage(0, 0);
    load_stage(1, 1);

    int scur = 0, snext = 1, sload = 2;
#pragma unroll 1
    for (int kt = 0; kt < 8; kt++) {
        if (kt < 7) { CPA_WAIT1(); } else { CPA_WAIT0(); }
        __syncthreads();
        if (kt + 2 < 8) load_stage(sload, kt + 2);
        compute(scur);
        const int t = scur; scur = snext; snext = sload; sload = t;
    }

    // Epilogue: rnd -> plain fp16; else fp32.
    const bool rnd = (round_mask >> wsel) & 1u;
    if (rnd) {
        __half* Ch = (__half*)Cv + (size_t)wsel * c_stride;
#pragma unroll
        for (int mt = 0; mt < 4; mt++) {
            const int row = m0 + wm * 64 + mt * 16 + r8;
#pragma unroll
            for (int nt = 0; nt < 8; nt++) {
                const int off = n0 + wn * 64 + nt * 8 + 2 * c;
                *(__half2*)&Ch[(size_t)row * 512 + off] =
                    __floats2half2_rn(acc[mt][nt][0], acc[mt][nt][1]);
                *(__half2*)&Ch[(size_t)(row + 8) * 512 + off] =
                    __floats2half2_rn(acc[mt][nt][2], acc[mt][nt][3]);
            }
        }
    } else {
        float* Cf = (float*)Cv;
#pragma unroll
        for (int mt = 0; mt < 4; mt++) {
            const int row = m0 + wm * 64 + mt * 16 + r8;
#pragma unroll
            for (int nt = 0; nt < 8; nt++) {
                const int col = n0 + wn * 64 + nt * 8 + 2 * c;
                *(float2*)&Cf[(size_t)row * 512 + col] =
                    make_float2(acc[mt][nt][0], acc[mt][nt][1]);
                *(float2*)&Cf[(size_t)(row + 8) * 512 + col] =
                    make_float2(acc[mt][nt][2], acc[mt][nt][3]);
            }
        }
    }
}

// ======================== attention (fp16 mma.sync + ldmatrix) =============
// One block (128 threads) per (batch, head). Q,K,V all plain fp16 rows.
// Row stride 40 halves (80B): chunk index 5i mod 8 is a permutation ->
// every ldmatrix phase is conflict-free. P stays in registers.
__global__ void __launch_bounds__(128, 8)
attn64_f16(const __half* __restrict__ Q, const __half* __restrict__ K,
           const __half* __restrict__ V, __half* __restrict__ At) {
    __shared__ __half Qs[64][40];
    __shared__ __half Ks[64][40];
    __shared__ __half Vs[64][40];

    const int tid  = threadIdx.x;
    const int lane = tid & 31;
    const int w    = tid >> 5;
    const int c    = lane & 3;
    const int r8   = lane >> 2;

    const int bh = blockIdx.x;
    const int b  = bh >> 4;
    const int h  = bh & 15;
    const size_t rbase = (size_t)b * SEQ * D_MODEL + h * DK;

    // Staging: thread = (row, half-of-row); plain 16B copies for Q,K,V.
    const int lrow = tid >> 1;
    const int part = tid & 1;
    {
        const __half* qp = Q + rbase + (size_t)lrow * D_MODEL + part * 16;
        const __half* kp = K + rbase + (size_t)lrow * D_MODEL + part * 16;
        const __half* vp = V + rbase + (size_t)lrow * D_MODEL + part * 16;
        *(uint4*)&Qs[lrow][part * 16]     = ((const uint4*)qp)[0];
        *(uint4*)&Qs[lrow][part * 16 + 8] = ((const uint4*)qp)[1];
        *(uint4*)&Ks[lrow][part * 16]     = ((const uint4*)kp)[0];
        *(uint4*)&Ks[lrow][part * 16 + 8] = ((const uint4*)kp)[1];
        *(uint4*)&Vs[lrow][part * 16]     = ((const uint4*)vp)[0];
        *(uint4*)&Vs[lrow][part * 16 + 8] = ((const uint4*)vp)[1];
    }
    __syncthreads();

    // ldmatrix lane-address components (bytes; row stride 80B).
    const int l7 = lane & 7;
    const int t01 = (lane >> 3) & 1;   // tile bit 0
    const int t23 = lane >> 4;         // tile bit 1

    // ---- S = Q K^T  (M=16/warp, N=64, K=32 -> 2 k16 groups) ----
    // A tiles: rows w*16 + t01*8, k-chunk t23.  K tiles: rows t23*8, k t01.
    const uint32_t aQ = smem_u32(&Qs[0][0]) +
                        (w * 16 + t01 * 8 + l7) * 80 + t23 * 16;
    const uint32_t bK = smem_u32(&Ks[0][0]) +
                        (t23 * 8 + l7) * 80 + t01 * 16;
    float s[8][4];
#pragma unroll
    for (int nt = 0; nt < 8; nt++)
#pragma unroll
        for (int i = 0; i < 4; i++) s[nt][i] = 0.0f;

#pragma unroll
    for (int g = 0; g < 2; g++) {
        uint32_t a0, a1, a2, a3;
        LDSM4(a0, a1, a2, a3, aQ + g * 32);
#pragma unroll
        for (int np = 0; np < 4; np++) {   // n-tile pairs (2 tiles each)
            uint32_t b0, b1, b2, b3;
            LDSM4(b0, b1, b2, b3, bK + np * (16 * 80) + g * 32);
            MMA_F16(s[2 * np],     a0, a1, a2, a3, b0, b1);
            MMA_F16(s[2 * np + 1], a0, a1, a2, a3, b2, b3);
        }
    }

    // ---- softmax ----
    const float scale = 0.17677669529663687f;  // 1/sqrt(32)
#pragma unroll
    for (int nt = 0; nt < 8; nt++)
#pragma unroll
        for (int i = 0; i < 4; i++) s[nt][i] *= scale;

    float m1 = -1e30f, m2 = -1e30f;
#pragma unroll
    for (int nt = 0; nt < 8; nt++) {
        m1 = fmaxf(m1, fmaxf(s[nt][0], s[nt][1]));
        m2 = fmaxf(m2, fmaxf(s[nt][2], s[nt][3]));
    }
    m1 = fmaxf(m1, __shfl_xor_sync(0xffffffffu, m1, 1));
    m1 = fmaxf(m1, __shfl_xor_sync(0xffffffffu, m1, 2));
    m2 = fmaxf(m2, __shfl_xor_sync(0xffffffffu, m2, 1));
    m2 = fmaxf(m2, __shfl_xor_sync(0xffffffffu, m2, 2));

    float sum1 = 0.0f, sum2 = 0.0f;
#pragma unroll
    for (int nt = 0; nt < 8; nt++) {
        s[nt][0] = __expf(s[nt][0] - m1);
        s[nt][1] = __expf(s[nt][1] - m1);
        s[nt][2] = __expf(s[nt][2] - m2);
        s[nt][3] = __expf(s[nt][3] - m2);
        sum1 += s[nt][0] + s[nt][1];
        sum2 += s[nt][2] + s[nt][3];
    }
    sum1 += __shfl_xor_sync(0xffffffffu, sum1, 1);
    sum1 += __shfl_xor_sync(0xffffffffu, sum1, 2);
    sum2 += __shfl_xor_sync(0xffffffffu, sum2, 1);
    sum2 += __shfl_xor_sync(0xffffffffu, sum2, 2);
    const float inv1 = 1.0f / sum1;
    const float inv2 = 1.0f / sum2;

    // ---- O = P V: P straight from registers; V B-frags via ldmatrix.trans.
    // V tiles for group g, dk-tile pair vp: rows g*16 + t01*8, cols
    // (vp*2 + t23)*8 dk -> bytes vp*32 + t23*16.
    const uint32_t bV = smem_u32(&Vs[0][0]) + (t01 * 8 + l7) * 80 + t23 * 16;
    float o[4][4];
#pragma unroll
    for (int nt = 0; nt < 4; nt++)
#pragma unroll
        for (int i = 0; i < 4; i++) o[nt][i] = 0.0f;

#pragma unroll
    for (int g = 0; g < 4; g++) {
        const uint32_t a0 = packh2(s[2 * g][0] * inv1, s[2 * g][1] * inv1);
        const uint32_t a1 = packh2(s[2 * g][2] * inv2, s[2 * g][3] * inv2);
        const uint32_t a2 = packh2(s[2 * g + 1][0] * inv1, s[2 * g + 1][1] * inv1);
        const uint32_t a3 = packh2(s[2 * g + 1][2] * inv2, s[2 * g + 1][3] * inv2);
#pragma unroll
        for (int vp = 0; vp < 2; vp++) {   // dk tile pairs
            uint32_t b0, b1, b2, b3;
            LDSM4T(b0, b1, b2, b3, bV + g * (16 * 80) + vp * 32);
            MMA_F16(o[2 * vp],     a0, a1, a2, a3, b0, b1);
            MMA_F16(o[2 * vp + 1], a0, a1, a2, a3, b2, b3);
        }
    }

    // Epilogue: fp16, pair-permuted (Wo-GEMM A-input layout).
    const int row = b * SEQ + w * 16 + r8;
#pragma unroll
    for (int nt = 0; nt < 4; nt++) {
        const int off = h * DK + (nt >> 1) * 16 + 4 * c + 2 * (nt & 1);
        *(__half2*)&At[(size_t)row * 512 + off] =
            __floats2half2_rn(o[nt][0], o[nt][1]);
        *(__half2*)&At[(size_t)(row + 8) * 512 + off] =
            __floats2half2_rn(o[nt][2], o[nt][3]);
    }
}

// ======================== launch ===========================================
extern "C" void kernel_launch(void* const* d_in, const int* in_sizes, int n_in,
                              void* d_out, int out_size) {
    (void)in_sizes; (void)n_in; (void)out_size;
    const float* x  = (const float*)d_in[0];
    const float* Wq = (const float*)d_in[1];
    const float* Wk = (const float*)d_in[2];
    const float* Wv = (const float*)d_in[3];
    const float* Wo = (const float*)d_in[4];
    float* out = (float*)d_out;

    void *pxh, *pwh, *pqkv, *pat;
    cudaGetSymbolAddress(&pxh, g_xh);
    cudaGetSymbolAddress(&pwh, g_wh);
    cudaGetSymbolAddress(&pqkv, g_qkvh);
    cudaGetSymbolAddress(&pat, g_ath);

    cudaFuncSetAttribute(gemm_f16,
                         cudaFuncAttributeMaxDynamicSharedMemorySize, GSMEM);

    prep_w_f2h<<<256, 256>>>(Wq, Wk, Wv, Wo, (__half*)pwh);
    prep_x_f2h<<<16384, 256>>>(x, (__half*)pxh);

    // Fused Q,K,V projections: all plain fp16.
    gemm_f16<<<dim3(12, M_ROWS / 128), 128, GSMEM>>>(
        (const __half*)pxh, (const __half*)pwh, pqkv, MS,
        /*round_mask=*/0b111u);

    const __half* q = (const __half*)pqkv;
    const __half* k = q + MS;
    const __half* v = k + MS;
    attn64_f16<<<M_ROWS / SEQ * NUM_HEADS, 128>>>(q, k, v, (__half*)pat);

    // Output projection: plain fp32 output.
    gemm_f16<<<dim3(4, M_ROWS / 128), 128, GSMEM>>>(
        (const __half*)pat, (const __half*)pwh + 3 * WELEMS, out, 0, 0u);
}

// round 11
// speedup vs baseline: 1.9992x; 1.0272x over previous
#include <cuda_runtime.h>
#include <cuda_fp16.h>
#include <cstdint>

// ---------------------------------------------------------------------------
// x:(2048,64,512) fp32, Wq/Wk/Wv/Wo:(512,512) fp32
// out = SDPA(x@WqT, x@WkT, x@WvT) @ WoT    H=16, dk=32, S=64
//
// R11: q,k,v and attn-out live in HEAD-MAJOR layout [b,h,s,dk] so the
// attention kernel's staging loads/stores are fully coalesced (the R10
// profile showed divergent 1KB-stride staging LDGs dominating L1).
// QKV GEMM epilogue scatters to head-major; Wo GEMM A-loader gathers from
// head-major. Fragment paths and all numerics unchanged.
// ---------------------------------------------------------------------------

#define D_MODEL   512
#define M_ROWS    131072
#define NUM_HEADS 16
#define SEQ       64
#define DK        32

#define MS        ((size_t)M_ROWS * D_MODEL)
#define WELEMS    ((size_t)D_MODEL * D_MODEL)

__device__ __half g_xh[MS];            // x, fp16, pair-permuted along k
__device__ __half g_wh[4 * WELEMS];    // Wq,Wk,Wv,Wo fp16, pair-permuted
__device__ __half g_qkvh[3 * MS];      // q, k, v : head-major [b,h,s,dk]
__device__ __half g_ath[MS];           // attn out: head-major, pair-permuted

// ======================== helpers ==========================================
__device__ __forceinline__ uint32_t smem_u32(const void* p) {
    uint32_t a;
    asm("{ .reg .u64 t; cvta.to.shared.u64 t, %1; cvt.u32.u64 %0, t; }"
        : "=r"(a) : "l"(p));
    return a;
}

#define MMA_F16(d, a0, a1, a2, a3, b0, b1)                                     \
    asm volatile(                                                              \
        "mma.sync.aligned.m16n8k16.row.col.f32.f16.f16.f32 "                   \
        "{%0,%1,%2,%3}, {%4,%5,%6,%7}, {%8,%9}, {%0,%1,%2,%3};"                \
        : "+f"(d[0]), "+f"(d[1]), "+f"(d[2]), "+f"(d[3])                       \
        : "r"(a0), "r"(a1), "r"(a2), "r"(a3), "r"(b0), "r"(b1))

#define LDSM4(r0, r1, r2, r3, a)                                               \
    asm volatile("ldmatrix.sync.aligned.m8n8.x4.shared.b16 "                   \
                 "{%0,%1,%2,%3}, [%4];"                                        \
                 : "=r"(r0), "=r"(r1), "=r"(r2), "=r"(r3) : "r"(a))
#define LDSM4T(r0, r1, r2, r3, a)                                              \
    asm volatile("ldmatrix.sync.aligned.m8n8.x4.trans.shared.b16 "             \
                 "{%0,%1,%2,%3}, [%4];"                                        \
                 : "=r"(r0), "=r"(r1), "=r"(r2), "=r"(r3) : "r"(a))

#define CPA16(sa, gp)                                                          \
    asm volatile("cp.async.cg.shared.global [%0], [%1], 16;"                   \
                 :: "r"(sa), "l"(gp) : "memory")
#define CPA_COMMIT() asm volatile("cp.async.commit_group;" ::: "memory")
#define CPA_WAIT1()  asm volatile("cp.async.wait_group 1;" ::: "memory")
#define CPA_WAIT0()  asm volatile("cp.async.wait_group 0;" ::: "memory")
#define LDS64(v, a)                                                            \
    asm volatile("ld.shared.v2.u32 {%0,%1}, [%2];"                             \
                 : "=r"((v).x), "=r"((v).y) : "r"(a))

__device__ __forceinline__ uint32_t packh2(float a, float b) {
    __half2 h = __floats2half2_rn(a, b);
    return *(uint32_t*)&h;
}

// Head-major address for logical (row=(b,s), col=(h,dk)) in halves.
__device__ __forceinline__ size_t hm_idx(int row, int col) {
    return ((size_t)(row >> 6) << 15) + ((size_t)(col >> 5) << 11) +
           ((size_t)(row & 63) << 5) + (size_t)(col & 31);
}

// ======================== prep: fp32 -> fp16 pair-permuted =================
__device__ __forceinline__ void prep16(const float* f, uint32_t* o) {
#pragma unroll
    for (int j = 0; j < 8; j++)
        o[((j & 3) << 1) + (j >> 2)] = packh2(f[2 * j], f[2 * j + 1]);
}

__global__ void __launch_bounds__(256)
prep_x_f2h(const float* __restrict__ in, __half* __restrict__ out) {
    size_t g = (size_t)blockIdx.x * 256 + threadIdx.x;   // group of 16
    float f[16];
#pragma unroll
    for (int q = 0; q < 4; q++)
        *(float4*)&f[4 * q] = ((const float4*)in)[4 * g + q];
    uint32_t o[8];
    prep16(f, o);
    ((uint4*)out)[2 * g]     = make_uint4(o[0], o[1], o[2], o[3]);
    ((uint4*)out)[2 * g + 1] = make_uint4(o[4], o[5], o[6], o[7]);
}

__global__ void __launch_bounds__(256)
prep_w_f2h(const float* __restrict__ w0, const float* __restrict__ w1,
           const float* __restrict__ w2, const float* __restrict__ w3,
           __half* __restrict__ out) {
    size_t g = (size_t)blockIdx.x * 256 + threadIdx.x;   // group of 16
    int wsel = (int)(g >> 14);                            // 16384 groups per W
    const float* src = wsel == 0 ? w0 : wsel == 1 ? w1 : wsel == 2 ? w2 : w3;
    size_t off = (g & 16383) * 16;
    float f[16];
#pragma unroll
    for (int q = 0; q < 4; q++)
        *(float4*)&f[4 * q] = ((const float4*)(src + off))[q];
    uint32_t o[8];
    prep16(f, o);
    ((uint4*)out)[2 * g]     = make_uint4(o[0], o[1], o[2], o[3]);
    ((uint4*)out)[2 * g + 1] = make_uint4(o[4], o[5], o[6], o[7]);
}

// ======================== GEMM (fp16 mma.sync, cp.async x3 stages) =========
// Block 128x128, BK=64 halves (128B/row), 128 threads = 4 warps (2Mx2N),
// warp tile 64x64. Stage = A(16KB)+B(16KB); 3 stages = 96KB; 2 CTAs/SM.
// a_hm: A gathered from head-major layout. c_hm: C scattered to head-major
// fp16 (QKV). Neither: C plain fp32 (final output).
#define GSTAGE  32768
#define GSMEM   (3 * GSTAGE + 128)

__global__ void __launch_bounds__(128, 2)
gemm_f16(const __half* __restrict__ A, const __half* __restrict__ Wt,
         void* __restrict__ Cv, size_t c_stride, int a_hm, int c_hm) {
    extern __shared__ char dsmem[];
    const uint32_t sb = (smem_u32(dsmem) + 127u) & ~127u;

    const int tid  = threadIdx.x;
    const int lane = tid & 31;
    const int wid  = tid >> 5;
    const int wm   = wid & 1;
    const int wn   = wid >> 1;
    const int c    = lane & 3;
    const int r8   = lane >> 2;

    const int nb   = blockIdx.x;
    const int wsel = nb >> 2;
    const int n0   = (nb & 3) * 128;
    const int m0   = blockIdx.y * 128;

    const __half* Aw = A + (size_t)m0 * 512;
    const __half* Bw = Wt + (size_t)wsel * WELEMS + (size_t)n0 * 512;

    float acc[4][8][4];
#pragma unroll
    for (int mt = 0; mt < 4; mt++)
#pragma unroll
        for (int nt = 0; nt < 8; nt++)
#pragma unroll
            for (int i = 0; i < 4; i++) acc[mt][nt][i] = 0.0f;

    auto load_stage = [&](int s, int kt) {
        const uint32_t stage = sb + s * GSTAGE;
#pragma unroll
        for (int i = 0; i < 16; i++) {
            const int cid = tid + i * 128;           // 0..2047 16B chunks
            const int isB = cid >> 10;
            const int r   = (cid >> 3) & 127;
            const int ch  = cid & 7;
            const uint32_t so =
                stage + isB * 16384 + r * 128 + (((ch ^ (r & 7)) << 4));
            const __half* gp;
            if (isB) {
                gp = Bw + (size_t)r * 512 + kt * 64 + ch * 8;
            } else if (!a_hm) {
                gp = Aw + (size_t)r * 512 + kt * 64 + ch * 8;
            } else {
                gp = A + hm_idx(m0 + r, kt * 64 + ch * 8);
            }
            CPA16(so, gp);
        }
        CPA_COMMIT();
    };

    auto compute = [&](int s) {
        const uint32_t sA = sb + s * GSTAGE + (wm * 64 + r8) * 128 + 8 * (c & 1);
        const uint32_t sB = sb + s * GSTAGE + 16384 + wn * 8192 + r8 * 128 +
                            8 * (c & 1);
#pragma unroll
        for (int g = 0; g < 4; g++) {
            const uint32_t csw = (uint32_t)(((2 * g + (c >> 1)) ^ r8) << 4);
            uint2 lo, hi;
            unsigned a0[4], a1[4], a2[4], a3[4], b0[8], b1[8];
#pragma unroll
            for (int mt = 0; mt < 4; mt++) {
                LDS64(lo, sA + mt * 2048 + csw);
                LDS64(hi, sA + mt * 2048 + 1024 + csw);
                a0[mt] = lo.x; a2[mt] = lo.y; a1[mt] = hi.x; a3[mt] = hi.y;
            }
#pragma unroll
            for (int nt = 0; nt < 8; nt++) {
                LDS64(lo, sB + nt * 1024 + csw);
                b0[nt] = lo.x; b1[nt] = lo.y;
            }
#pragma unroll
            for (int mt = 0; mt < 4; mt++)
#pragma unroll
                for (int nt = 0; nt < 8; nt++)
                    MMA_F16(acc[mt][nt], a0[mt], a1[mt], a2[mt], a3[mt],
                            b0[nt], b1[nt]);
        }
    };

    load_stage(0, 0);
    load_stage(1, 1);

    int scur = 0, snext = 1, sload = 2;
#pragma unroll 1
    for (int kt = 0; kt < 8; kt++) {
        if (kt < 7) { CPA_WAIT1(); } else { CPA_WAIT0(); }
        __syncthreads();
        if (kt + 2 < 8) load_stage(sload, kt + 2);
        compute(scur);
        const int t = scur; scur = snext; snext = sload; sload = t;
    }

    // Epilogue.
    if (c_hm) {
        __half* Ch = (__half*)Cv + (size_t)wsel * c_stride;
#pragma unroll
        for (int mt = 0; mt < 4; mt++) {
            const int row = m0 + wm * 64 + mt * 16 + r8;
#pragma unroll
            for (int nt = 0; nt < 8; nt++) {
                const int off = n0 + wn * 64 + nt * 8 + 2 * c;
                const size_t a = hm_idx(row, off);
                *(__half2*)&Ch[a] =
                    __floats2half2_rn(acc[mt][nt][0], acc[mt][nt][1]);
                *(__half2*)&Ch[a + 256] =   // row+8 -> s+8 -> +8*32 halves
                    __floats2half2_rn(acc[mt][nt][2], acc[mt][nt][3]);
            }
        }
    } else {
        float* Cf = (float*)Cv;
#pragma unroll
        for (int mt = 0; mt < 4; mt++) {
            const int row = m0 + wm * 64 + mt * 16 + r8;
#pragma unroll
            for (int nt = 0; nt < 8; nt++) {
                const int col = n0 + wn * 64 + nt * 8 + 2 * c;
                *(float2*)&Cf[(size_t)row * 512 + col] =
                    make_float2(acc[mt][nt][0], acc[mt][nt][1]);
                *(float2*)&Cf[(size_t)(row + 8) * 512 + col] =
                    make_float2(acc[mt][nt][2], acc[mt][nt][3]);
            }
        }
    }
}

// ======================== attention (fp16 mma.sync + ldmatrix) =============
// One block (128 threads) per (batch, head). q,k,v head-major: each tensor
// slab for this block is 4KB CONTIGUOUS -> fully coalesced staging.
// Row stride 40 halves (80B) keeps every ldmatrix phase conflict-free.
// P stays in registers (S-fragment == PV A-fragment).
__global__ void __launch_bounds__(128, 8)
attn64_f16(const __half* __restrict__ Q, const __half* __restrict__ K,
           const __half* __restrict__ V, __half* __restrict__ At) {
    __shared__ __half Qs[64][40];
    __shared__ __half Ks[64][40];
    __shared__ __half Vs[64][40];

    const int tid  = threadIdx.x;
    const int lane = tid & 31;
    const int w    = tid >> 5;
    const int c    = lane & 3;
    const int r8   = lane >> 2;

    const int bh = blockIdx.x;                 // b*16 + h
    const size_t base = (size_t)bh * 2048;     // [b,h] slab, 64x32 halves

    // Staging: 4KB per tensor = 256 16B chunks; thread handles chunks
    // tid and tid+128. Fully coalesced LDG.128.
    {
        const uint4* qg = (const uint4*)(Q + base);
        const uint4* kg = (const uint4*)(K + base);
        const uint4* vg = (const uint4*)(V + base);
#pragma unroll
        for (int i = 0; i < 2; i++) {
            const int ci  = tid + i * 128;
            const int row = ci >> 2, p = ci & 3;
            *(uint4*)&Qs[row][p * 8] = qg[ci];
            *(uint4*)&Ks[row][p * 8] = kg[ci];
            *(uint4*)&Vs[row][p * 8] = vg[ci];
        }
    }
    __syncthreads();

    // ldmatrix lane-address components (bytes; row stride 80B).
    const int l7  = lane & 7;
    const int t01 = (lane >> 3) & 1;   // tile bit 0
    const int t23 = lane >> 4;         // tile bit 1

    // ---- S = Q K^T  (M=16/warp, N=64, K=32 -> 2 k16 groups) ----
    const uint32_t aQ = smem_u32(&Qs[0][0]) +
                        (w * 16 + t01 * 8 + l7) * 80 + t23 * 16;
    const uint32_t bK = smem_u32(&Ks[0][0]) +
                        (t23 * 8 + l7) * 80 + t01 * 16;
    float s[8][4];
#pragma unroll
    for (int nt = 0; nt < 8; nt++)
#pragma unroll
        for (int i = 0; i < 4; i++) s[nt][i] = 0.0f;

#pragma unroll
    for (int g = 0; g < 2; g++) {
        uint32_t a0, a1, a2, a3;
        LDSM4(a0, a1, a2, a3, aQ + g * 32);
#pragma unroll
        for (int np = 0; np < 4; np++) {   // n-tile pairs (2 tiles each)
            uint32_t b0, b1, b2, b3;
            LDSM4(b0, b1, b2, b3, bK + np * (16 * 80) + g * 32);
            MMA_F16(s[2 * np],     a0, a1, a2, a3, b0, b1);
            MMA_F16(s[2 * np + 1], a0, a1, a2, a3, b2, b3);
        }
    }

    // ---- softmax ----
    const float scale = 0.17677669529663687f;  // 1/sqrt(32)
#pragma unroll
    for (int nt = 0; nt < 8; nt++)
#pragma unroll
        for (int i = 0; i < 4; i++) s[nt][i] *= scale;

    float m1 = -1e30f, m2 = -1e30f;
#pragma unroll
    for (int nt = 0; nt < 8; nt++) {
        m1 = fmaxf(m1, fmaxf(s[nt][0], s[nt][1]));
        m2 = fmaxf(m2, fmaxf(s[nt][2], s[nt][3]));
    }
    m1 = fmaxf(m1, __shfl_xor_sync(0xffffffffu, m1, 1));
    m1 = fmaxf(m1, __shfl_xor_sync(0xffffffffu, m1, 2));
    m2 = fmaxf(m2, __shfl_xor_sync(0xffffffffu, m2, 1));
    m2 = fmaxf(m2, __shfl_xor_sync(0xffffffffu, m2, 2));

    float sum1 = 0.0f, sum2 = 0.0f;
#pragma unroll
    for (int nt = 0; nt < 8; nt++) {
        s[nt][0] = __expf(s[nt][0] - m1);
        s[nt][1] = __expf(s[nt][1] - m1);
        s[nt][2] = __expf(s[nt][2] - m2);
        s[nt][3] = __expf(s[nt][3] - m2);
        sum1 += s[nt][0] + s[nt][1];
        sum2 += s[nt][2] + s[nt][3];
    }
    sum1 += __shfl_xor_sync(0xffffffffu, sum1, 1);
    sum1 += __shfl_xor_sync(0xffffffffu, sum1, 2);
    sum2 += __shfl_xor_sync(0xffffffffu, sum2, 1);
    sum2 += __shfl_xor_sync(0xffffffffu, sum2, 2);
    const float inv1 = 1.0f / sum1;
    const float inv2 = 1.0f / sum2;

    // ---- O = P V: P straight from registers; V B-frags via ldmatrix.trans.
    const uint32_t bV = smem_u32(&Vs[0][0]) + (t01 * 8 + l7) * 80 + t23 * 16;
    float o[4][4];
#pragma unroll
    for (int nt = 0; nt < 4; nt++)
#pragma unroll
        for (int i = 0; i < 4; i++) o[nt][i] = 0.0f;

#pragma unroll
    for (int g = 0; g < 4; g++) {
        const uint32_t a0 = packh2(s[2 * g][0] * inv1, s[2 * g][1] * inv1);
        const uint32_t a1 = packh2(s[2 * g][2] * inv2, s[2 * g][3] * inv2);
        const uint32_t a2 = packh2(s[2 * g + 1][0] * inv1, s[2 * g + 1][1] * inv1);
        const uint32_t a3 = packh2(s[2 * g + 1][2] * inv2, s[2 * g + 1][3] * inv2);
#pragma unroll
        for (int vp = 0; vp < 2; vp++) {   // dk tile pairs
            uint32_t b0, b1, b2, b3;
            LDSM4T(b0, b1, b2, b3, bV + g * (16 * 80) + vp * 32);
            MMA_F16(o[2 * vp],     a0, a1, a2, a3, b0, b1);
            MMA_F16(o[2 * vp + 1], a0, a1, a2, a3, b2, b3);
        }
    }

    // Epilogue: head-major, pair-permuted within the 32-dk block
    // (Wo-GEMM A-input layout). Coalesced 64B-stride rows.
    const int srow = w * 16 + r8;
#pragma unroll
    for (int nt = 0; nt < 4; nt++) {
        const int off = (nt >> 1) * 16 + 4 * c + 2 * (nt & 1);
        *(__half2*)&At[base + srow * 32 + off] =
            __floats2half2_rn(o[nt][0], o[nt][1]);
        *(__half2*)&At[base + (srow + 8) * 32 + off] =
            __floats2half2_rn(o[nt][2], o[nt][3]);
    }
}

// ======================== launch ===========================================
extern "C" void kernel_launch(void* const* d_in, const int* in_sizes, int n_in,
                              void* d_out, int out_size) {
    (void)in_sizes; (void)n_in; (void)out_size;
    const float* x  = (const float*)d_in[0];
    const float* Wq = (const float*)d_in[1];
    const float* Wk = (const float*)d_in[2];
    const float* Wv = (const float*)d_in[3];
    const float* Wo = (const float*)d_in[4];
    float* out = (float*)d_out;

    void *pxh, *pwh, *pqkv, *pat;
    cudaGetSymbolAddress(&pxh, g_xh);
    cudaGetSymbolAddress(&pwh, g_wh);
    cudaGetSymbolAddress(&pqkv, g_qkvh);
    cudaGetSymbolAddress(&pat, g_ath);

    cudaFuncSetAttribute(gemm_f16,
                         cudaFuncAttributeMaxDynamicSharedMemorySize, GSMEM);

    prep_w_f2h<<<256, 256>>>(Wq, Wk, Wv, Wo, (__half*)pwh);
    prep_x_f2h<<<16384, 256>>>(x, (__half*)pxh);

    // Fused Q,K,V projections -> head-major fp16.
    gemm_f16<<<dim3(12, M_ROWS / 128), 128, GSMEM>>>(
        (const __half*)pxh, (const __half*)pwh, pqkv, MS,
        /*a_hm=*/0, /*c_hm=*/1);

    const __half* q = (const __half*)pqkv;
    const __half* k = q + MS;
    const __half* v = k + MS;
    attn64_f16<<<M_ROWS / SEQ * NUM_HEADS, 128>>>(q, k, v, (__half*)pat);

    // Output projection: gather head-major A, plain fp32 output.
    gemm_f16<<<dim3(4, M_ROWS / 128), 128, GSMEM>>>(
        (const __half*)pat, (const __half*)pwh + 3 * WELEMS, out, 0,
        /*a_hm=*/1, /*c_hm=*/0);
}